// round 1
// baseline (speedup 1.0000x reference)
#include <cuda_runtime.h>

#define W_IMG 1248
#define H_IMG 384
#define B_IMG 2
#define NROWS (B_IMG * H_IMG)   // 768
#define DISP_NUM 192
#define NT 256                  // threads per block
#define CHUNK ((W_IMG + NT - 1) / NT)  // 5

__global__ __launch_bounds__(NT) void stereo_prefix_kernel(
    const float* __restrict__ L,
    const float* __restrict__ R,
    float* __restrict__ out)
{
    const int row = blockIdx.x;            // 0..767 (b*H + h), C==1 so rows are contiguous
    const float* __restrict__ r = R + (size_t)row * W_IMG;
    const float* __restrict__ l = L + (size_t)row * W_IMG;
    float* __restrict__ o = out + (size_t)row * W_IMG;

    // Exclusive prefix arrays: P[k] = sum_{j<k} r[j], Q[k] = sum_{j<k} j*r[j]
    __shared__ double P[W_IMG + 1];
    __shared__ double Q[W_IMG + 1];
    __shared__ double WP[NT / 32], WQ[NT / 32];

    const int t = threadIdx.x;
    const int lane = t & 31;
    const int warp = t >> 5;

    const int start = t * CHUNK;
    const int end = min(start + CHUNK, W_IMG);

    // 1) local serial scan of this thread's chunk (inclusive, stored at index+1)
    double sp = 0.0, sq = 0.0;
    #pragma unroll
    for (int j = start; j < end; j++) {
        double rv = (double)r[j];
        sp += rv;
        sq += (double)j * rv;
        P[j + 1] = sp;
        Q[j + 1] = sq;
    }

    // 2) inclusive warp scan of thread totals (sp, sq)
    double vp = sp, vq = sq;
    #pragma unroll
    for (int off = 1; off < 32; off <<= 1) {
        double pp = __shfl_up_sync(0xffffffffu, vp, off);
        double qq = __shfl_up_sync(0xffffffffu, vq, off);
        if (lane >= off) { vp += pp; vq += qq; }
    }
    if (lane == 31) { WP[warp] = vp; WQ[warp] = vq; }
    __syncthreads();

    // 3) scan the 8 warp totals (warp 0, lanes 0-7)
    if (warp == 0 && lane < (NT / 32)) {
        double a = WP[lane], b = WQ[lane];
        #pragma unroll
        for (int off = 1; off < (NT / 32); off <<= 1) {
            double pa = __shfl_up_sync(0x000000ffu, a, off);
            double pb = __shfl_up_sync(0x000000ffu, b, off);
            if (lane >= off) { a += pa; b += pb; }
        }
        WP[lane] = a; WQ[lane] = b;
    }
    __syncthreads();

    // 4) add exclusive offset (everything before this thread's chunk)
    double offP = (vp - sp) + (warp > 0 ? WP[warp - 1] : 0.0);
    double offQ = (vq - sq) + (warp > 0 ? WQ[warp - 1] : 0.0);
    #pragma unroll
    for (int j = start; j < end; j++) {
        P[j + 1] += offP;
        Q[j + 1] += offQ;
    }
    if (t == 0) { P[0] = 0.0; Q[0] = 0.0; }
    __syncthreads();

    // 5) outputs: S[w] = w*(P[w+1]-P[lo]) - (Q[w+1]-Q[lo]), lo = max(0, w-191)
    for (int w = t; w < W_IMG; w += NT) {
        int lo = w - (DISP_NUM - 1);
        if (lo < 0) lo = 0;
        double dP = P[w + 1] - P[lo];
        double dQ = Q[w + 1] - Q[lo];
        float s = (float)((double)w * dP - dQ);
        o[w] = l[w] * s;
    }
}

extern "C" void kernel_launch(void* const* d_in, const int* in_sizes, int n_in,
                              void* d_out, int out_size)
{
    const float* left  = (const float*)d_in[0];
    const float* right = (const float*)d_in[1];
    float* out = (float*)d_out;
    stereo_prefix_kernel<<<NROWS, NT>>>(left, right, out);
}

// round 2
// speedup vs baseline: 4.5282x; 4.5282x over previous
#include <cuda_runtime.h>

#define W_IMG 1248
#define NROWS 768
#define T_TILE 208
#define NTILES 6            // 6 * 208 = 1248
#define NT 192              // 6 warps: one warp per tile
#define CHUNK 7             // ceil(208 / 32)

__global__ __launch_bounds__(NT) void stereo_tile_kernel(
    const float* __restrict__ L,
    const float* __restrict__ R,
    float* __restrict__ out)
{
    __shared__ float rs[W_IMG];
    __shared__ float2 PQ[NTILES][T_TILE + 1];   // exclusive prefix: PQ[t][0] = 0

    const int row = blockIdx.x;
    const float* __restrict__ r = R + (size_t)row * W_IMG;
    const float* __restrict__ l = L + (size_t)row * W_IMG;
    float* __restrict__ o = out + (size_t)row * W_IMG;

    const int t = threadIdx.x;
    const int lane = t & 31;
    const int warp = t >> 5;

    // Stage r into shared, fully coalesced (7 strided passes of 192 threads)
    #pragma unroll
    for (int s = 0; s < 7; s++) {
        int idx = t + NT * s;
        if (idx < W_IMG) rs[idx] = r[idx];
    }
    __syncthreads();

    // Each warp builds local prefix sums for its tile (fp32, local coords)
    {
        const int ts = warp * T_TILE;
        const int k0 = lane * CHUNK;

        float p = 0.f, q = 0.f;
        float lp[CHUNK], lq[CHUNK];
        #pragma unroll
        for (int s = 0; s < CHUNK; s++) {
            int k = k0 + s;
            float rv = (k < T_TILE) ? rs[ts + k] : 0.f;
            p += rv;
            q = fmaf((float)k, rv, q);
            lp[s] = p;
            lq[s] = q;
        }

        // inclusive warp scan of thread totals
        float vp = p, vq = q;
        #pragma unroll
        for (int off = 1; off < 32; off <<= 1) {
            float ap = __shfl_up_sync(0xffffffffu, vp, off);
            float aq = __shfl_up_sync(0xffffffffu, vq, off);
            if (lane >= off) { vp += ap; vq += aq; }
        }
        const float offp = vp - p;    // exclusive offset for this thread's chunk
        const float offq = vq - q;

        #pragma unroll
        for (int s = 0; s < CHUNK; s++) {
            int k = k0 + s;
            if (k < T_TILE)
                PQ[warp][k + 1] = make_float2(lp[s] + offp, lq[s] + offq);
        }
        if (lane == 0) PQ[warp][0] = make_float2(0.f, 0.f);
    }
    __syncthreads();

    // Outputs: each window spans at most the current tile + previous tile
    #pragma unroll
    for (int s = 0; s < 7; s++) {
        int w = t + NT * s;
        if (w < W_IMG) {
            int tile = w / T_TILE;
            int i = w - tile * T_TILE;

            float2 a = PQ[tile][i + 1];
            float S;
            if (i >= 191) {
                // window [w-191, w] entirely inside current tile
                float2 b = PQ[tile][i - 191];
                S = (float)i * (a.x - b.x) - (a.y - b.y);
            } else {
                // current-tile part: j = ts .. w
                S = (float)i * a.x - a.y;
                if (tile > 0) {
                    // previous-tile part: local k' = i+17 .. 207, weight (i+208-k')
                    float2 tot = PQ[tile - 1][T_TILE];
                    float2 c = PQ[tile - 1][i + 17];
                    S += (float)(i + T_TILE) * (tot.x - c.x) - (tot.y - c.y);
                }
            }
            o[w] = l[w] * S;
        }
    }
}

extern "C" void kernel_launch(void* const* d_in, const int* in_sizes, int n_in,
                              void* d_out, int out_size)
{
    const float* left  = (const float*)d_in[0];
    const float* right = (const float*)d_in[1];
    float* out = (float*)d_out;
    stereo_tile_kernel<<<NROWS, NT>>>(left, right, out);
}

// round 3
// speedup vs baseline: 5.1991x; 1.1481x over previous
#include <cuda_runtime.h>

#define W_IMG 1248
#define NROWS 768
#define T_TILE 256
#define NTILES 5
#define NT 160                 // 5 warps, one per 256-wide tile
#define CHUNK 8
#define MIDX(i) ((((i) & 7) << 5) + ((i) >> 3))   // bank-conflict-free permutation

__global__ __launch_bounds__(NT) void stereo_tile2_kernel(
    const float* __restrict__ L,
    const float* __restrict__ R,
    float* __restrict__ out)
{
    // Inclusive local prefix sums, permuted layout: PQ[tile][m(i)] = (P[i+1], Q[i+1])
    __shared__ float2 PQ[NTILES][T_TILE];

    const int row = blockIdx.x;
    const float* __restrict__ r = R + (size_t)row * W_IMG;
    const float* __restrict__ l = L + (size_t)row * W_IMG;
    float* __restrict__ o = out + (size_t)row * W_IMG;

    const int t    = threadIdx.x;
    const int lane = t & 31;
    const int warp = t >> 5;
    const int k0   = lane * CHUNK;            // local index base within tile
    const int g0   = warp * T_TILE + k0;      // global column base
    const bool inr = g0 < W_IMG;              // whole 8-chunk in/out (1248 % 8 == 0)

    // Issue all 4 vector loads up front (MLP=4, l prefetched alongside r)
    float4 r0, r1, l0, l1;
    if (inr) {
        r0 = *(const float4*)(r + g0);
        r1 = *(const float4*)(r + g0 + 4);
        l0 = *(const float4*)(l + g0);
        l1 = *(const float4*)(l + g0 + 4);
    } else {
        r0 = r1 = l0 = l1 = make_float4(0.f, 0.f, 0.f, 0.f);
    }

    // Local serial scan of the 8-element chunk (local tile coordinates)
    float rv[8] = {r0.x, r0.y, r0.z, r0.w, r1.x, r1.y, r1.z, r1.w};
    float lp[8], lq[8];
    float p = 0.f, q = 0.f;
    #pragma unroll
    for (int s = 0; s < 8; s++) {
        p += rv[s];
        q = fmaf((float)(k0 + s), rv[s], q);
        lp[s] = p;
        lq[s] = q;
    }

    // Inclusive warp scan of thread totals
    float vp = p, vq = q;
    #pragma unroll
    for (int off = 1; off < 32; off <<= 1) {
        float ap = __shfl_up_sync(0xffffffffu, vp, off);
        float aq = __shfl_up_sync(0xffffffffu, vq, off);
        if (lane >= off) { vp += ap; vq += aq; }
    }
    const float offp = vp - p;
    const float offq = vq - q;

    // Publish inclusive prefixes (conflict-free: write index = s*32 + lane)
    #pragma unroll
    for (int s = 0; s < 8; s++) {
        lp[s] += offp;
        lq[s] += offq;
        PQ[warp][MIDX(k0 + s)] = make_float2(lp[s], lq[s]);
    }
    __syncthreads();

    if (inr) {
        float2 tot = make_float2(0.f, 0.f);
        if (warp > 0) tot = PQ[warp - 1][MIDX(T_TILE - 1)];   // prev-tile totals (broadcast)

        float res[8];
        #pragma unroll
        for (int s = 0; s < 8; s++) {
            const int i = k0 + s;          // local coordinate of output w = warp*256 + i
            float S;
            if (i >= 192) {
                // window [i-191, i] entirely inside this tile
                float2 b = PQ[warp][MIDX(i - 192)];
                S = (float)i * (lp[s] - b.x) - (lq[s] - b.y);
            } else {
                // in-tile part: j = 0..i   (at i==191 the cross part self-cancels)
                S = (float)i * lp[s] - lq[s];
                if (warp > 0) {
                    // prev-tile part: local k' = i+65 .. 255, weight (i+256-k')
                    float2 c = PQ[warp - 1][MIDX(i + 64)];
                    S += (float)(i + T_TILE) * (tot.x - c.x) - (tot.y - c.y);
                }
            }
            res[s] = S;
        }

        float4 o0 = make_float4(res[0] * l0.x, res[1] * l0.y, res[2] * l0.z, res[3] * l0.w);
        float4 o1 = make_float4(res[4] * l1.x, res[5] * l1.y, res[6] * l1.z, res[7] * l1.w);
        *(float4*)(o + g0)     = o0;
        *(float4*)(o + g0 + 4) = o1;
    }
}

extern "C" void kernel_launch(void* const* d_in, const int* in_sizes, int n_in,
                              void* d_out, int out_size)
{
    const float* left  = (const float*)d_in[0];
    const float* right = (const float*)d_in[1];
    float* out = (float*)d_out;
    stereo_tile2_kernel<<<NROWS, NT>>>(left, right, out);
}